// round 10
// baseline (speedup 1.0000x reference)
#include <cuda_runtime.h>
#include <cstdint>

// ---------------------------------------------------------------------------
// PrunedGroupSum: y[b,g] = (sum over contiguous column group g of x[b,:]) / 20
//   x:           [B, D] float32   (B=1024, D=262144 -> 1 GiB, streaming)
//   group_sizes: [K]    int32     (K=1000, sums to D)
//   out:         [B, K] float32
//
// R10: R7 exactly (block = (group, 32 rows), warp = 8-row slice, unroll-2
// -> 16 independent LDG.128 live, launch_bounds(128,5)) + LPT scheduling:
// builder bitonic-sorts groups by size descending and blockIdx.x maps to
// sorted order, so the longest blocks launch in wave 0 and short ones
// backfill the tail (R7's residual = inter-block straggler waves).
// ---------------------------------------------------------------------------

#define MAX_K 4096
#define ROWS_PER_WARP 8
#define ROWS_PER_BLOCK 32
#define SORT_N 1024

__device__ int g_offsets[MAX_K + 1];
__device__ int g_order[SORT_N];   // group ids sorted by size, descending

// 1-block builder: prefix scan -> offsets, bitonic sort (desc) -> g_order.
// Requires K <= 1024 (K=1000 here).
__global__ void pgs_build_kernel(const int* __restrict__ gs, int K) {
    __shared__ int sh[SORT_N];
    __shared__ int key[SORT_N];
    __shared__ int val[SORT_N];
    int t = threadIdx.x;

    // ---- scan: group offsets ----
    int v = (t < K) ? gs[t] : 0;
    sh[t] = v;
    __syncthreads();
#pragma unroll
    for (int off = 1; off < SORT_N; off <<= 1) {
        int add = (t >= off) ? sh[t - off] : 0;
        __syncthreads();
        sh[t] += add;
        __syncthreads();
    }
    if (t == 0) g_offsets[0] = 0;
    if (t < K) g_offsets[t + 1] = sh[t];

    // ---- bitonic sort by size, descending ----
    key[t] = (t < K) ? gs[t] : -1;   // pad sorts to the end
    val[t] = t;
    __syncthreads();

    for (int k = 2; k <= SORT_N; k <<= 1) {
        for (int j = k >> 1; j > 0; j >>= 1) {
            int ixj = t ^ j;
            if (ixj > t) {
                bool desc_block = ((t & k) == 0);
                int kt = key[t], ki = key[ixj];
                bool swap = desc_block ? (kt < ki) : (kt > ki);
                if (swap) {
                    int vt = val[t];
                    key[t] = ki; key[ixj] = kt;
                    val[t] = val[ixj]; val[ixj] = vt;
                }
            }
            __syncthreads();
        }
    }
    g_order[t] = val[t];
}

__device__ __forceinline__ float hsum4(float4 v) {
    return (v.x + v.y) + (v.z + v.w);
}

__global__ __launch_bounds__(128, 5) void pgs_sum_kernel(
    const float* __restrict__ x,
    float* __restrict__ out,
    int D, int K, int B)
{
    int g = g_order[blockIdx.x];
    int warp = threadIdx.x >> 5;
    int lane = threadIdx.x & 31;

    int row0 = blockIdx.y * ROWS_PER_BLOCK + warp * ROWS_PER_WARP;
    int nrows = B - row0;
    if (nrows <= 0) return;
    if (nrows > ROWS_PER_WARP) nrows = ROWS_PER_WARP;

    int s = g_offsets[g];
    int e = g_offsets[g + 1];

    const float* p = x + (size_t)row0 * (size_t)D;
    const size_t SD = (size_t)D;

    float acc[ROWS_PER_WARP];
#pragma unroll
    for (int r = 0; r < ROWS_PER_WARP; r++) acc[r] = 0.0f;

    int s4 = (s + 3) & ~3;
    int e4 = e & ~3;

    if (nrows == ROWS_PER_WARP) {
        if (s4 >= e4) {
            // tiny group: scalar, coalesced across lanes, 8 streams
            for (int c = s + lane; c < e; c += 32) {
#pragma unroll
                for (int r = 0; r < ROWS_PER_WARP; r++)
                    acc[r] += __ldcs(p + (size_t)r * SD + c);
            }
        } else {
            // head (<=3 scalar cols)
            {
                int c = s + lane;
                if (c < s4) {
#pragma unroll
                    for (int r = 0; r < ROWS_PER_WARP; r++)
                        acc[r] += __ldcs(p + (size_t)r * SD + c);
                }
            }
            int c4 = s4 + lane * 4;
            // unroll-2 main: 16 independent LDG.128 live at once
            for (; c4 + 128 < e4; c4 += 256) {
                float4 v[ROWS_PER_WARP];
                float4 w[ROWS_PER_WARP];
#pragma unroll
                for (int r = 0; r < ROWS_PER_WARP; r++)
                    v[r] = __ldcs(reinterpret_cast<const float4*>(p + (size_t)r * SD + c4));
#pragma unroll
                for (int r = 0; r < ROWS_PER_WARP; r++)
                    w[r] = __ldcs(reinterpret_cast<const float4*>(p + (size_t)r * SD + c4 + 128));
#pragma unroll
                for (int r = 0; r < ROWS_PER_WARP; r++)
                    acc[r] += hsum4(v[r]) + hsum4(w[r]);
            }
            // remainder vector tile (0 or 1 per lane)
            if (c4 < e4) {
                float4 v[ROWS_PER_WARP];
#pragma unroll
                for (int r = 0; r < ROWS_PER_WARP; r++)
                    v[r] = __ldcs(reinterpret_cast<const float4*>(p + (size_t)r * SD + c4));
#pragma unroll
                for (int r = 0; r < ROWS_PER_WARP; r++)
                    acc[r] += hsum4(v[r]);
            }
            // tail (<=3 scalar cols)
            {
                int c = e4 + lane;
                if (c < e) {
#pragma unroll
                    for (int r = 0; r < ROWS_PER_WARP; r++)
                        acc[r] += __ldcs(p + (size_t)r * SD + c);
                }
            }
        }
    } else {
        // remainder rows (B not multiple of 32): scalar per-row path
        for (int r = 0; r < nrows; r++) {
            const float* pr = p + (size_t)r * SD;
            float a = 0.f;
            for (int c = s + lane; c < e; c += 32) a += __ldcs(pr + c);
            acc[r] = a;
        }
    }

    // butterfly reduce all 8 accumulators
#pragma unroll
    for (int r = 0; r < ROWS_PER_WARP; r++) {
#pragma unroll
        for (int o = 16; o > 0; o >>= 1)
            acc[r] += __shfl_xor_sync(0xffffffffu, acc[r], o);
    }

    if (lane == 0) {
        const float inv_tau = 1.0f / 20.0f;
        size_t ob = (size_t)row0 * (size_t)K + g;
#pragma unroll
        for (int r = 0; r < ROWS_PER_WARP; r++)
            if (r < nrows) out[ob + (size_t)r * (size_t)K] = acc[r] * inv_tau;
    }
}

extern "C" void kernel_launch(void* const* d_in, const int* in_sizes, int n_in,
                              void* d_out, int out_size) {
    const float* x  = (const float*)d_in[0];
    const int*   gs = (const int*)d_in[1];

    int K = in_sizes[1];
    int B = out_size / K;
    int D = in_sizes[0] / B;

    float* out = (float*)d_out;

    pgs_build_kernel<<<1, SORT_N>>>(gs, K);

    dim3 grid(K, (B + ROWS_PER_BLOCK - 1) / ROWS_PER_BLOCK);
    pgs_sum_kernel<<<grid, 128>>>(x, out, D, K, B);
}

// round 11
// speedup vs baseline: 1.1100x; 1.1100x over previous
#include <cuda_runtime.h>
#include <cstdint>

// ---------------------------------------------------------------------------
// PrunedGroupSum: y[b,g] = (sum over contiguous column group g of x[b,:]) / 20
//   x:           [B, D] float32   (B=1024, D=262144 -> 1 GiB, streaming)
//   group_sizes: [K]    int32     (K=1000, sums to D)
//   out:         [B, K] float32
//
// R11: uniform data-domain tiling. Block = (32 rows x 2048 cols) -> every
// block does identical load work (no imbalance at any level) and adjacent
// concurrent blocks stream adjacent memory (R10 proved this locality is
// worth ~10% DRAM). Warp = 8-row slice (R7's proven MLP structure, unroll-2
// inside segments). Group segmentation handled per warp: binary search for
// the first overlapping group, then per-segment reduce + fire-and-forget
// RED.ADD into zero-initialized out.
// ---------------------------------------------------------------------------

#define MAX_K 4096
#define ROWS_PER_WARP 8
#define ROWS_PER_BLOCK 32
#define TILE_COLS 2048

__device__ int g_offsets[MAX_K + 1];

// 1-block Hillis-Steele inclusive scan of group_sizes (K <= 1024; K=1000 here).
__global__ void pgs_scan_kernel(const int* __restrict__ gs, int K) {
    __shared__ int sh[1024];
    int t = threadIdx.x;
    int v = (t < K) ? gs[t] : 0;
    sh[t] = v;
    __syncthreads();
#pragma unroll
    for (int off = 1; off < 1024; off <<= 1) {
        int add = (t >= off) ? sh[t - off] : 0;
        __syncthreads();
        sh[t] += add;
        __syncthreads();
    }
    if (t == 0) g_offsets[0] = 0;
    if (t < K) g_offsets[t + 1] = sh[t];
}

__global__ void pgs_zero_kernel(float* __restrict__ out, int n) {
    int i = blockIdx.x * blockDim.x + threadIdx.x;
    if (i < n) out[i] = 0.0f;
}

__device__ __forceinline__ float hsum4(float4 v) {
    return (v.x + v.y) + (v.z + v.w);
}

__global__ __launch_bounds__(128, 5) void pgs_tile_kernel(
    const float* __restrict__ x,
    float* __restrict__ out,
    int D, int K, int B)
{
    int warp = threadIdx.x >> 5;
    int lane = threadIdx.x & 31;

    int tile_lo = blockIdx.x * TILE_COLS;
    int tile_hi = tile_lo + TILE_COLS;
    if (tile_hi > D) tile_hi = D;

    int row0 = blockIdx.y * ROWS_PER_BLOCK + warp * ROWS_PER_WARP;
    int nrows = B - row0;
    if (nrows <= 0) return;
    if (nrows > ROWS_PER_WARP) nrows = ROWS_PER_WARP;

    // binary search: first group g with g_offsets[g+1] > tile_lo
    int lo = 0, hi = K - 1;
    while (lo < hi) {
        int mid = (lo + hi) >> 1;
        if (g_offsets[mid + 1] > tile_lo) hi = mid; else lo = mid + 1;
    }
    int g = lo;

    const float* p = x + (size_t)row0 * (size_t)D;
    const size_t SD = (size_t)D;
    const float inv_tau = 1.0f / 20.0f;

    // walk all group-segments intersecting this tile
    while (g < K) {
        int gs_ = g_offsets[g];
        if (gs_ >= tile_hi) break;
        int ge_ = g_offsets[g + 1];
        int s = gs_ > tile_lo ? gs_ : tile_lo;
        int e = ge_ < tile_hi ? ge_ : tile_hi;

        float acc[ROWS_PER_WARP];
#pragma unroll
        for (int r = 0; r < ROWS_PER_WARP; r++) acc[r] = 0.0f;

        int s4 = (s + 3) & ~3;
        int e4 = e & ~3;

        if (nrows == ROWS_PER_WARP) {
            if (s4 >= e4) {
                // tiny segment: scalar, coalesced across lanes, 8 streams
                for (int c = s + lane; c < e; c += 32) {
#pragma unroll
                    for (int r = 0; r < ROWS_PER_WARP; r++)
                        acc[r] += __ldcs(p + (size_t)r * SD + c);
                }
            } else {
                // head (<=3 scalar cols)
                {
                    int c = s + lane;
                    if (c < s4) {
#pragma unroll
                        for (int r = 0; r < ROWS_PER_WARP; r++)
                            acc[r] += __ldcs(p + (size_t)r * SD + c);
                    }
                }
                int c4 = s4 + lane * 4;
                // unroll-2 main: 16 independent LDG.128 live at once
                for (; c4 + 128 < e4; c4 += 256) {
                    float4 v[ROWS_PER_WARP];
                    float4 w[ROWS_PER_WARP];
#pragma unroll
                    for (int r = 0; r < ROWS_PER_WARP; r++)
                        v[r] = __ldcs(reinterpret_cast<const float4*>(p + (size_t)r * SD + c4));
#pragma unroll
                    for (int r = 0; r < ROWS_PER_WARP; r++)
                        w[r] = __ldcs(reinterpret_cast<const float4*>(p + (size_t)r * SD + c4 + 128));
#pragma unroll
                    for (int r = 0; r < ROWS_PER_WARP; r++)
                        acc[r] += hsum4(v[r]) + hsum4(w[r]);
                }
                // remainder vector tile (0 or 1 per lane)
                if (c4 < e4) {
                    float4 v[ROWS_PER_WARP];
#pragma unroll
                    for (int r = 0; r < ROWS_PER_WARP; r++)
                        v[r] = __ldcs(reinterpret_cast<const float4*>(p + (size_t)r * SD + c4));
#pragma unroll
                    for (int r = 0; r < ROWS_PER_WARP; r++)
                        acc[r] += hsum4(v[r]);
                }
                // tail (<=3 scalar cols)
                {
                    int c = e4 + lane;
                    if (c < e) {
#pragma unroll
                        for (int r = 0; r < ROWS_PER_WARP; r++)
                            acc[r] += __ldcs(p + (size_t)r * SD + c);
                    }
                }
            }
        } else {
            // remainder rows (B not multiple of 32): scalar per-row path
            for (int r = 0; r < nrows; r++) {
                const float* pr = p + (size_t)r * SD;
                float a = 0.f;
                for (int c = s + lane; c < e; c += 32) a += __ldcs(pr + c);
                acc[r] = a;
            }
        }

        // butterfly reduce all 8 accumulators
#pragma unroll
        for (int r = 0; r < ROWS_PER_WARP; r++) {
#pragma unroll
            for (int o = 16; o > 0; o >>= 1)
                acc[r] += __shfl_xor_sync(0xffffffffu, acc[r], o);
        }

        if (lane == 0) {
            float* ob = out + (size_t)row0 * (size_t)K + g;
#pragma unroll
            for (int r = 0; r < ROWS_PER_WARP; r++)
                if (r < nrows) atomicAdd(ob + (size_t)r * (size_t)K, acc[r] * inv_tau);
        }

        g++;
    }
}

extern "C" void kernel_launch(void* const* d_in, const int* in_sizes, int n_in,
                              void* d_out, int out_size) {
    const float* x  = (const float*)d_in[0];
    const int*   gs = (const int*)d_in[1];

    int K = in_sizes[1];
    int B = out_size / K;
    int D = in_sizes[0] / B;

    float* out = (float*)d_out;

    pgs_scan_kernel<<<1, 1024>>>(gs, K);
    pgs_zero_kernel<<<(out_size + 255) / 256, 256>>>(out, out_size);

    dim3 grid((D + TILE_COLS - 1) / TILE_COLS,
              (B + ROWS_PER_BLOCK - 1) / ROWS_PER_BLOCK);
    pgs_tile_kernel<<<grid, 128>>>(x, out, D, K, B);
}

// round 12
// speedup vs baseline: 1.2143x; 1.0939x over previous
#include <cuda_runtime.h>
#include <cstdint>

// ---------------------------------------------------------------------------
// PrunedGroupSum: y[b,g] = (sum over contiguous column group g of x[b,:]) / 20
//   x:           [B, D] float32   (B=1024, D=262144 -> 1 GiB, streaming)
//   group_sizes: [K]    int32     (K=1000, sums to D)
//   out:         [B, K] float32
//
// R12: main kernel = R7 verbatim (best measured: 168.6us, DRAM 80.8%,
// block = (group, 32 rows), warp = 8-row slice, unroll-2 -> 16 independent
// LDG.128 live, launch_bounds(128,5), no atomics). Prologue replaced by a
// single-warp shuffle scan (zero __syncthreads, ~1us vs 5us Hillis-Steele).
// ---------------------------------------------------------------------------

#define MAX_K 4096
#define ROWS_PER_WARP 8
#define ROWS_PER_BLOCK 32

__device__ int g_offsets[MAX_K + 1];

// Single-warp scan: lane l serially sums gs[32l .. 32l+31] (int4 loads),
// shuffle-scan of the 32 lane totals gives lane bases, then lanes write the
// running prefix for their 32 elements. Requires K <= 1024 (K=1000 here).
__global__ void pgs_scan_warp_kernel(const int* __restrict__ gs, int K) {
    int lane = threadIdx.x;          // 32 threads
    int base = lane * 32;

    int v[32];
#pragma unroll
    for (int i = 0; i < 32; i += 4) {
        int idx = base + i;
        int4 t = make_int4(0, 0, 0, 0);
        if (idx + 3 < K) {
            t = *reinterpret_cast<const int4*>(gs + idx);
        } else {
            if (idx     < K) t.x = gs[idx];
            if (idx + 1 < K) t.y = gs[idx + 1];
            if (idx + 2 < K) t.z = gs[idx + 2];
            if (idx + 3 < K) t.w = gs[idx + 3];
        }
        v[i] = t.x; v[i + 1] = t.y; v[i + 2] = t.z; v[i + 3] = t.w;
    }

    int total = 0;
#pragma unroll
    for (int i = 0; i < 32; i++) total += v[i];

    // exclusive shuffle-scan of lane totals
    int run = total;
#pragma unroll
    for (int o = 1; o < 32; o <<= 1) {
        int n = __shfl_up_sync(0xffffffffu, run, o);
        if (lane >= o) run += n;
    }
    int lane_base = run - total;     // exclusive prefix for this lane

    if (lane == 0) g_offsets[0] = 0;
    int acc = lane_base;
#pragma unroll
    for (int i = 0; i < 32; i++) {
        acc += v[i];
        int idx = base + i;
        if (idx < K) g_offsets[idx + 1] = acc;
    }
}

__device__ __forceinline__ float hsum4(float4 v) {
    return (v.x + v.y) + (v.z + v.w);
}

__global__ __launch_bounds__(128, 5) void pgs_sum_kernel(
    const float* __restrict__ x,
    float* __restrict__ out,
    int D, int K, int B)
{
    int g = blockIdx.x;
    int warp = threadIdx.x >> 5;
    int lane = threadIdx.x & 31;

    int row0 = blockIdx.y * ROWS_PER_BLOCK + warp * ROWS_PER_WARP;
    int nrows = B - row0;
    if (nrows <= 0) return;
    if (nrows > ROWS_PER_WARP) nrows = ROWS_PER_WARP;

    int s = g_offsets[g];
    int e = g_offsets[g + 1];

    const float* p = x + (size_t)row0 * (size_t)D;
    const size_t SD = (size_t)D;

    float acc[ROWS_PER_WARP];
#pragma unroll
    for (int r = 0; r < ROWS_PER_WARP; r++) acc[r] = 0.0f;

    int s4 = (s + 3) & ~3;
    int e4 = e & ~3;

    if (nrows == ROWS_PER_WARP) {
        if (s4 >= e4) {
            // tiny group: scalar, coalesced across lanes, 8 streams
            for (int c = s + lane; c < e; c += 32) {
#pragma unroll
                for (int r = 0; r < ROWS_PER_WARP; r++)
                    acc[r] += __ldcs(p + (size_t)r * SD + c);
            }
        } else {
            // head (<=3 scalar cols)
            {
                int c = s + lane;
                if (c < s4) {
#pragma unroll
                    for (int r = 0; r < ROWS_PER_WARP; r++)
                        acc[r] += __ldcs(p + (size_t)r * SD + c);
                }
            }
            int c4 = s4 + lane * 4;
            // unroll-2 main: 16 independent LDG.128 live at once
            for (; c4 + 128 < e4; c4 += 256) {
                float4 v[ROWS_PER_WARP];
                float4 w[ROWS_PER_WARP];
#pragma unroll
                for (int r = 0; r < ROWS_PER_WARP; r++)
                    v[r] = __ldcs(reinterpret_cast<const float4*>(p + (size_t)r * SD + c4));
#pragma unroll
                for (int r = 0; r < ROWS_PER_WARP; r++)
                    w[r] = __ldcs(reinterpret_cast<const float4*>(p + (size_t)r * SD + c4 + 128));
#pragma unroll
                for (int r = 0; r < ROWS_PER_WARP; r++)
                    acc[r] += hsum4(v[r]) + hsum4(w[r]);
            }
            // remainder vector tile (0 or 1 per lane)
            if (c4 < e4) {
                float4 v[ROWS_PER_WARP];
#pragma unroll
                for (int r = 0; r < ROWS_PER_WARP; r++)
                    v[r] = __ldcs(reinterpret_cast<const float4*>(p + (size_t)r * SD + c4));
#pragma unroll
                for (int r = 0; r < ROWS_PER_WARP; r++)
                    acc[r] += hsum4(v[r]);
            }
            // tail (<=3 scalar cols)
            {
                int c = e4 + lane;
                if (c < e) {
#pragma unroll
                    for (int r = 0; r < ROWS_PER_WARP; r++)
                        acc[r] += __ldcs(p + (size_t)r * SD + c);
                }
            }
        }
    } else {
        // remainder rows (B not multiple of 32): scalar per-row path
        for (int r = 0; r < nrows; r++) {
            const float* pr = p + (size_t)r * SD;
            float a = 0.f;
            for (int c = s + lane; c < e; c += 32) a += __ldcs(pr + c);
            acc[r] = a;
        }
    }

    // butterfly reduce all 8 accumulators
#pragma unroll
    for (int r = 0; r < ROWS_PER_WARP; r++) {
#pragma unroll
        for (int o = 16; o > 0; o >>= 1)
            acc[r] += __shfl_xor_sync(0xffffffffu, acc[r], o);
    }

    if (lane == 0) {
        const float inv_tau = 1.0f / 20.0f;
        size_t ob = (size_t)row0 * (size_t)K + g;
#pragma unroll
        for (int r = 0; r < ROWS_PER_WARP; r++)
            if (r < nrows) out[ob + (size_t)r * (size_t)K] = acc[r] * inv_tau;
    }
}

extern "C" void kernel_launch(void* const* d_in, const int* in_sizes, int n_in,
                              void* d_out, int out_size) {
    const float* x  = (const float*)d_in[0];
    const int*   gs = (const int*)d_in[1];

    int K = in_sizes[1];
    int B = out_size / K;
    int D = in_sizes[0] / B;

    float* out = (float*)d_out;

    pgs_scan_warp_kernel<<<1, 32>>>(gs, K);

    dim3 grid(K, (B + ROWS_PER_BLOCK - 1) / ROWS_PER_BLOCK);
    pgs_sum_kernel<<<grid, 128>>>(x, out, D, K, B);
}